// round 15
// baseline (speedup 1.0000x reference)
#include <cuda_runtime.h>
#include <cuda_bf16.h>
#include <math.h>
#include <stdint.h>

#define B_   2
#define S_   2048
#define HID  2048
#define NH   16
#define HD   128
#define RK   64
#define BS_ROWS (B_*S_)        // 4096
#define HROWS   (B_*S_*NH)     // 65536

// ===================== scratch (static __device__) =====================
__device__ __nv_bfloat16 g_hs_h[BS_ROWS*HID],  g_hs_l[BS_ROWS*HID];
__device__ __nv_bfloat16 g_WqT_h[HID*HID], g_WqT_l[HID*HID];
__device__ __nv_bfloat16 g_WkT_h[HID*HID], g_WkT_l[HID*HID];
__device__ __nv_bfloat16 g_WoT_h[HID*HID], g_WoT_l[HID*HID];
__device__ __nv_bfloat16 g_MvT_h[1024*HID], g_MvT_l[1024*HID];   // folded (Wv·Wvc)^T
__device__ __nv_bfloat16 g_Qr_h[BS_ROWS*HID], g_Qr_l[BS_ROWS*HID];
__device__ __nv_bfloat16 g_Kr_h[BS_ROWS*HID], g_Kr_l[BS_ROWS*HID];
__device__ __nv_bfloat16 g_Wcat_h[256*HD], g_Wcat_l[256*HD];   // [Wqa|Wqg]^T padded
__device__ __nv_bfloat16 g_WkcT_h[256*HD], g_WkcT_l[256*HD];   // rows 128+ stay 0
__device__ __nv_bfloat16 g_WovT_h[256*RK], g_WovT_l[256*RK];   // rows 128+ stay 0
__device__ __nv_bfloat16 g_qa_h[HROWS*RK], g_qa_l[HROWS*RK];   // pre-scaled 1/8
__device__ __nv_bfloat16 g_kc_h[HROWS*RK], g_kc_l[HROWS*RK];
__device__ __nv_bfloat16 g_vc_h[HROWS*RK], g_vc_l[HROWS*RK];
__device__ float g_qg[HROWS*HD];
__device__ __nv_bfloat16 g_oc_h[HROWS*RK], g_oc_l[HROWS*RK];
__device__ __nv_bfloat16 g_gat_h[BS_ROWS*HID], g_gat_l[BS_ROWS*HID];
__device__ float g_cos[S_*32], g_sin[S_*32];

// ===================== PTX helpers =====================
__device__ __forceinline__ uint32_t smem_u32(const void* p) {
    uint32_t a;
    asm("{ .reg .u64 t; cvta.to.shared.u64 t, %1; cvt.u32.u64 %0, t; }" : "=r"(a) : "l"(p));
    return a;
}
__device__ __forceinline__ void cpasync16(uint32_t dst, const void* src) {
    asm volatile("cp.async.cg.shared.global [%0], [%1], 16;" :: "r"(dst), "l"(src));
}
__device__ __forceinline__ void ldsm4(uint32_t* r, uint32_t addr) {
    asm volatile("ldmatrix.sync.aligned.m8n8.x4.shared.b16 {%0,%1,%2,%3}, [%4];"
        : "=r"(r[0]), "=r"(r[1]), "=r"(r[2]), "=r"(r[3]) : "r"(addr));
}
__device__ __forceinline__ void ldsm4t(uint32_t* r, uint32_t addr) {
    asm volatile("ldmatrix.sync.aligned.m8n8.x4.trans.shared.b16 {%0,%1,%2,%3}, [%4];"
        : "=r"(r[0]), "=r"(r[1]), "=r"(r[2]), "=r"(r[3]) : "r"(addr));
}
__device__ __forceinline__ void mma16816(float* c, const uint32_t* a, const uint32_t* b) {
    asm volatile(
        "mma.sync.aligned.m16n8k16.row.col.f32.bf16.bf16.f32 "
        "{%0,%1,%2,%3}, {%4,%5,%6,%7}, {%8,%9}, {%0,%1,%2,%3};"
        : "+f"(c[0]), "+f"(c[1]), "+f"(c[2]), "+f"(c[3])
        : "r"(a[0]), "r"(a[1]), "r"(a[2]), "r"(a[3]), "r"(b[0]), "r"(b[1]));
}
__device__ __forceinline__ void bsplit(float v, __nv_bfloat16& h, __nv_bfloat16& l) {
    h = __float2bfloat16(v);
    l = __float2bfloat16(v - __bfloat162float(h));
}
__device__ __forceinline__ void packsplit(float lo, float hi, uint32_t& ph, uint32_t& pl) {
    __nv_bfloat16 hl = __float2bfloat16(lo), hh = __float2bfloat16(hi);
    ph = (uint32_t)__bfloat16_as_ushort(hl) | ((uint32_t)__bfloat16_as_ushort(hh) << 16);
    __nv_bfloat16 ll = __float2bfloat16(lo - __bfloat162float(hl));
    __nv_bfloat16 lh = __float2bfloat16(hi - __bfloat162float(hh));
    pl = (uint32_t)__bfloat16_as_ushort(ll) | ((uint32_t)__bfloat16_as_ushort(lh) << 16);
}

// ===================== prep kernels =====================
__global__ void prep_misc(const int* __restrict__ pos,
                          const float* __restrict__ Wqa, const float* __restrict__ Wqg,
                          const float* __restrict__ Wkc, const float* __restrict__ Wov) {
    int idx = blockIdx.x * blockDim.x + threadIdx.x;
    if (idx < S_ * 32) {
        int s = idx >> 5, i = idx & 31;
        float p = (float)pos[s];
        float inv = 1.0f / powf(10000.0f, (float)(2 * i) * (1.0f / 64.0f));
        float a = p * inv;
        g_cos[idx] = cosf(a);
        g_sin[idx] = sinf(a);
    }
    if (idx < 32768) {                 // cat: 256 rows x 128
        int n = idx >> 7, k = idx & 127;
        float v = (n < 64) ? Wqa[k * 64 + n] : (n < 192) ? Wqg[k * 128 + (n - 64)] : 0.f;
        __nv_bfloat16 h, l; bsplit(v, h, l);
        g_Wcat_h[idx] = h; g_Wcat_l[idx] = l;
    } else if (idx < 49152) {          // kc: rows 0..127 (64 real + zeros); 128+ stay 0
        int i2 = idx - 32768;
        int n = i2 >> 7, k = i2 & 127;
        float v = (n < 64) ? Wkc[k * 64 + n] : 0.f;
        __nv_bfloat16 h, l; bsplit(v, h, l);
        g_WkcT_h[i2] = h; g_WkcT_l[i2] = l;
    } else if (idx < 57344) {          // ov: rows 0..127; 128+ stay 0
        int i2 = idx - 49152;
        int n = i2 >> 6, k = i2 & 63;
        __nv_bfloat16 h, l; bsplit(Wov[k * 128 + n], h, l);
        g_WovT_h[i2] = h; g_WovT_l[i2] = l;
    }
}

__global__ void split2(const float* __restrict__ in, __nv_bfloat16* oh, __nv_bfloat16* ol, int n) {
    for (int i = blockIdx.x * blockDim.x + threadIdx.x; i < n; i += gridDim.x * blockDim.x) {
        __nv_bfloat16 h, l; bsplit(in[i], h, l); oh[i] = h; ol[i] = l;
    }
}

#define PREPW_SMEM 66560
__global__ void prep_weights(const float* __restrict__ Wq, const float* __restrict__ Wk,
                             const float* __restrict__ Wo,
                             const float* __restrict__ Wv, const float* __restrict__ Wvc) {
    extern __shared__ float fsm[];
    const int gid = blockIdx.x;
    const int t = threadIdx.x;
    if (gid < 12288) {
        int z = gid >> 12, rem = gid & 4095;
        int bx = rem & 63, by = rem >> 6;
        const float* in = (z == 0) ? Wq : (z == 1) ? Wk : Wo;
        __nv_bfloat16* dh = (z == 0) ? g_WqT_h : (z == 1) ? g_WkT_h : g_WoT_h;
        __nv_bfloat16* dl = (z == 0) ? g_WqT_l : (z == 1) ? g_WkT_l : g_WoT_l;
        float (*tt)[33] = (float(*)[33])fsm;
        int x = t & 31, y = t >> 5;
        int bc = bx * 32, br = by * 32;
#pragma unroll
        for (int j = 0; j < 32; j += 8)
            tt[y + j][x] = in[(size_t)(br + y + j) * HID + bc + x];
        __syncthreads();
#pragma unroll
        for (int j = 0; j < 32; j += 8) {
            float v = tt[x][y + j];
            __nv_bfloat16 h, l; bsplit(v, h, l);
            size_t o = (size_t)(bc + y + j) * HID + br + x;
            dh[o] = h; dl[o] = l;
        }
    } else {
        int fid = gid - 12288;
        int e0 = (fid & 31) * 64, h = fid >> 5;
        float* sWv = fsm;
        float* sVc = fsm + 8192;
        for (int i = t; i < 8192; i += 256) {
            int e = i >> 7, d = i & 127;
            sWv[i] = Wv[(size_t)(e0 + e) * HID + h * HD + d];
        }
        for (int i = t; i < 8192; i += 256) {
            int r = i & 63, d = i >> 6;
            sVc[r * 132 + d] = Wvc[d * 64 + r];
        }
        __syncthreads();
        const int r = t & 63, eg = t >> 6;
        float acc[16];
#pragma unroll
        for (int ei = 0; ei < 16; ei++) acc[ei] = 0.f;
        for (int d = 0; d < 128; d += 4) {
            float4 v4 = *(float4*)&sVc[r * 132 + d];
#pragma unroll
            for (int ei = 0; ei < 16; ei++) {
                float4 w4 = *(float4*)&sWv[(eg * 16 + ei) * 128 + d];
                acc[ei] += w4.x * v4.x + w4.y * v4.y + w4.z * v4.z + w4.w * v4.w;
            }
        }
        size_t base = (size_t)(h * 64 + r) * HID + e0 + eg * 16;
#pragma unroll
        for (int ei = 0; ei < 16; ei++) {
            __nv_bfloat16 hh, ll; bsplit(acc[ei], hh, ll);
            g_MvT_h[base + ei] = hh; g_MvT_l[base + ei] = ll;
        }
    }
}

// ============ split-bf16 warp-MMA GEMM: 128x256 tile, 512 thr ============
// 16 warps (4m x 4n), warp tile 32x64, KC=64, 2-stage cp.async.
// Stage: Ah 16K | Al 16K | Bh 32K | Bl 32K = 96K. MMA:LDSM ratio = 4.
#define NTHR    512
#define STAGE_B 98304
#define GSMEM   (2 * STAGE_B)
#define SCW     260    // sC stride (floats)

__device__ __forceinline__ void mainloop_sC(
    const __nv_bfloat16* __restrict__ Ah, const __nv_bfloat16* __restrict__ Al,
    const __nv_bfloat16* __restrict__ Bh, const __nv_bfloat16* __restrict__ Bl,
    int Kdim, char* smem, int row0, int n0)
{
    const uint32_t sb = smem_u32(smem);
    const int tid  = threadIdx.x;
    const int wid  = tid >> 5, lane = tid & 31;
    const int wm   = wid >> 2, wn = wid & 3;

    float acc[2][8][4];
#pragma unroll
    for (int mi = 0; mi < 2; mi++)
#pragma unroll
        for (int ni = 0; ni < 8; ni++)
#pragma unroll
            for (int j = 0; j < 4; j++) acc[mi][ni][j] = 0.f;

    const int NIT = Kdim >> 6;

    auto load_chunk = [&](int it, int s) {
        const int kc0 = it << 6;
        const uint32_t base = sb + (uint32_t)s * STAGE_B;
        // A: 128 rows x 8 granules (h + l)
#pragma unroll
        for (int q = 0; q < 2; q++) {
            int g = tid + q * NTHR;
            int r = g >> 3, cg = g & 7;
            uint32_t sw = (uint32_t)(r * 128 + ((cg ^ (r & 7)) << 4));
            size_t ga = (size_t)(row0 + r) * Kdim + kc0 + cg * 8;
            cpasync16(base +         sw, Ah + ga);
            cpasync16(base + 16384 + sw, Al + ga);
        }
        // B: 256 rows x 8 granules (h + l)
#pragma unroll
        for (int q = 0; q < 4; q++) {
            int g = tid + q * NTHR;
            int r = g >> 3, cg = g & 7;
            uint32_t sw = (uint32_t)(r * 128 + ((cg ^ (r & 7)) << 4));
            size_t gb = (size_t)(n0 + r) * Kdim + kc0 + cg * 8;
            cpasync16(base + 32768 + sw, Bh + gb);
            cpasync16(base + 65536 + sw, Bl + gb);
        }
        asm volatile("cp.async.commit_group;" ::: "memory");
    };

    auto compute = [&](int s) {
        const uint32_t aB = sb + (uint32_t)s * STAGE_B;
        const uint32_t bB = aB + 32768;
#pragma unroll
        for (int ks = 0; ks < 4; ks++) {
            uint32_t ahf[2][4], alf[2][4];
#pragma unroll
            for (int mi = 0; mi < 2; mi++) {
                int r  = wm * 32 + mi * 16 + (lane & 15);
                int cg = ks * 2 + (lane >> 4);
                uint32_t sw = (uint32_t)(r * 128 + ((cg ^ (r & 7)) << 4));
                ldsm4(ahf[mi], aB + sw);
                ldsm4(alf[mi], aB + 16384 + sw);
            }
            // B in 4 groups of 16 cols (2 n-frags) to bound registers
#pragma unroll
            for (int g4 = 0; g4 < 4; g4++) {
                int r  = wn * 64 + g4 * 16 + (lane & 15);
                int cg = ks * 2 + (lane >> 4);
                uint32_t sw = (uint32_t)(r * 128 + ((cg ^ (r & 7)) << 4));
                uint32_t th[4], tl[4];
                ldsm4(th, bB + sw);
                ldsm4(tl, bB + 32768 + sw);
                uint32_t bh0[2] = {th[0], th[2]}, bh1[2] = {th[1], th[3]};
                uint32_t bl0[2] = {tl[0], tl[2]}, bl1[2] = {tl[1], tl[3]};
#pragma unroll
                for (int mi = 0; mi < 2; mi++) {
                    mma16816(acc[mi][g4*2],   ahf[mi], bh0);
                    mma16816(acc[mi][g4*2],   ahf[mi], bl0);
                    mma16816(acc[mi][g4*2],   alf[mi], bh0);
                    mma16816(acc[mi][g4*2+1], ahf[mi], bh1);
                    mma16816(acc[mi][g4*2+1], ahf[mi], bl1);
                    mma16816(acc[mi][g4*2+1], alf[mi], bh1);
                }
            }
        }
    };

    load_chunk(0, 0);
    for (int it = 0; it < NIT; ++it) {
        if (it + 1 < NIT) {
            load_chunk(it + 1, (it + 1) & 1);
            asm volatile("cp.async.wait_group 1;" ::: "memory");
        } else {
            asm volatile("cp.async.wait_group 0;" ::: "memory");
        }
        __syncthreads();
        compute(it & 1);
        __syncthreads();   // protect stage (it&1) before next prefetch overwrites
    }

    float* sC = (float*)smem;
#pragma unroll
    for (int mi = 0; mi < 2; mi++)
#pragma unroll
        for (int ni = 0; ni < 8; ni++) {
            int m0 = wm * 32 + mi * 16 + (lane >> 2);
            int c0 = wn * 64 + ni * 8 + (lane & 3) * 2;
            sC[m0 * SCW + c0]           = acc[mi][ni][0];
            sC[m0 * SCW + c0 + 1]       = acc[mi][ni][1];
            sC[(m0 + 8) * SCW + c0]     = acc[mi][ni][2];
            sC[(m0 + 8) * SCW + c0 + 1] = acc[mi][ni][3];
        }
    __syncthreads();
}

// Epilogues over sC[128][SCW]. Modes:
// 0 fp32 out; 1 split; 2 rope+split; 3 qa(split x0.125)|qg fp32; 4 silu(qg)*v split
__device__ __forceinline__ void epilogue(
    int mode, int Nvalid, int ostride,
    float* __restrict__ outf, __nv_bfloat16* __restrict__ oh, __nv_bfloat16* __restrict__ ol,
    char* smem, int row0, int n0)
{
    float* sC = (float*)smem;
    const int tid = threadIdx.x;
    for (int x = tid; x < 128 * 256; x += NTHR) {
        int r = x >> 8, c = x & 255;
        int gr = row0 + r, gc = n0 + c;
        if (gc >= Nvalid) continue;
        float v = sC[r * SCW + c];
        if (mode == 0) {
            outf[(size_t)gr * ostride + gc] = v;
        } else if (mode == 1) {
            __nv_bfloat16 h, l; bsplit(v, h, l);
            size_t o = (size_t)gr * ostride + gc; oh[o] = h; ol[o] = l;
        } else if (mode == 2) {
            int d = gc & 127;
            float outv = v;
            if (d < 64) {
                int i = d & 31;
                int sdx = (gr & (S_ - 1)) * 32 + i;
                float co = g_cos[sdx], si = g_sin[sdx];
                float p = (d < 32) ? sC[r * SCW + c + 32] : sC[r * SCW + c - 32];
                outv = (d < 32) ? v * co - p * si : v * co + p * si;
            }
            __nv_bfloat16 h, l; bsplit(outv, h, l);
            size_t o = (size_t)gr * ostride + gc; oh[o] = h; ol[o] = l;
        } else if (mode == 3) {
            if (gc < 64) {
                __nv_bfloat16 h, l; bsplit(v * 0.125f, h, l);
                size_t o = (size_t)gr * 64 + gc; oh[o] = h; ol[o] = l;
            } else g_qg[(size_t)gr * 128 + (gc - 64)] = v;
        } else { // 4
            float g = g_qg[(size_t)gr * 128 + gc];
            float sil = g / (1.0f + expf(-g));
            __nv_bfloat16 h, l; bsplit(sil * v, h, l);
            size_t o = (size_t)gr * 128 + gc; oh[o] = h; ol[o] = l;
        }
    }
}

__global__ __launch_bounds__(NTHR) void gemm_one(
    const __nv_bfloat16* Ah, const __nv_bfloat16* Al,
    const __nv_bfloat16* Bh, const __nv_bfloat16* Bl,
    int Kdim, int mode, int Nvalid, int ostride,
    float* outf, __nv_bfloat16* oh, __nv_bfloat16* ol)
{
    extern __shared__ __align__(128) char smem[];
    const int r0 = blockIdx.x * 128, c0 = blockIdx.y * 256;
    mainloop_sC(Ah, Al, Bh, Bl, Kdim, smem, r0, c0);
    epilogue(mode, Nvalid, ostride, outf, oh, ol, smem, r0, c0);
}

// Q (rope+split -> Qr), K (rope+split -> Kr), V-folded (split vc): grid (32,8,3)
__global__ __launch_bounds__(NTHR) void gemm_qkv(
    const __nv_bfloat16* Ah, const __nv_bfloat16* Al)
{
    extern __shared__ __align__(128) char smem[];
    const int r0 = blockIdx.x * 128, c0 = blockIdx.y * 256;
    const int z = blockIdx.z;
    if (z == 2 && blockIdx.y >= 4) return;
    const __nv_bfloat16* Bh = (z == 0) ? g_WqT_h : (z == 1) ? g_WkT_h : g_MvT_h;
    const __nv_bfloat16* Bl = (z == 0) ? g_WqT_l : (z == 1) ? g_WkT_l : g_MvT_l;
    mainloop_sC(Ah, Al, Bh, Bl, HID, smem, r0, c0);
    if (z == 0)      epilogue(2, HID, HID, nullptr, g_Qr_h, g_Qr_l, smem, r0, c0);
    else if (z == 1) epilogue(2, HID, HID, nullptr, g_Kr_h, g_Kr_l, smem, r0, c0);
    else             epilogue(1, 1024, 1024, nullptr, g_vc_h, g_vc_l, smem, r0, c0);
}

// head projections: z0 qa|qg (A=Qr as [65536x128], B=Wcat), z1 kc (A=Kr, B=WkcT)
__global__ __launch_bounds__(NTHR) void gemm_heads()
{
    extern __shared__ __align__(128) char smem[];
    const int r0 = blockIdx.x * 128;
    if (blockIdx.z == 0) {
        mainloop_sC(g_Qr_h, g_Qr_l, g_Wcat_h, g_Wcat_l, 128, smem, r0, 0);
        epilogue(3, 192, 0, nullptr, g_qa_h, g_qa_l, smem, r0, 0);
    } else {
        mainloop_sC(g_Kr_h, g_Kr_l, g_WkcT_h, g_WkcT_l, 128, smem, r0, 0);
        epilogue(1, 64, 64, nullptr, g_kc_h, g_kc_l, smem, r0, 0);
    }
}

// ===================== tensor-core flash attention (unchanged) ===========
#define ATT_SMEM (32768 + 2 * 65536)

__global__ __launch_bounds__(256, 1) void attn_mma()
{
    extern __shared__ __align__(128) char smem[];
    const uint32_t sb = smem_u32(smem);
    const int tid = threadIdx.x, wid = tid >> 5, lane = tid & 31;
    const int b = blockIdx.y >> 4, h = blockIdx.y & 15;
    const int q0 = blockIdx.x * 128;

    for (int i = tid; i < 1024; i += 256) {
        int r = i >> 3, g = i & 7;
        uint32_t sw = (uint32_t)(r * 128 + ((g ^ (r & 7)) << 4));
        size_t gl = ((size_t)((b * S_ + q0 + r) * NH + h)) * RK + g * 8;
        cpasync16(sb + sw,         g_qa_h + gl);
        cpasync16(sb + 16384 + sw, g_qa_l + gl);
    }
    auto load_kv = [&](int t, int s) {
        const uint32_t kb = sb + 32768 + (uint32_t)s * 65536;
        for (int i = tid; i < 1024; i += 256) {
            int r = i >> 3, g = i & 7;
            uint32_t sw = (uint32_t)(r * 128 + ((g ^ (r & 7)) << 4));
            size_t gl = ((size_t)((b * S_ + t * 128 + r) * NH + h)) * RK + g * 8;
            cpasync16(kb + sw,         g_kc_h + gl);
            cpasync16(kb + 16384 + sw, g_kc_l + gl);
            cpasync16(kb + 32768 + sw, g_vc_h + gl);
            cpasync16(kb + 49152 + sw, g_vc_l + gl);
        }
    };
    load_kv(0, 0);
    asm volatile("cp.async.commit_group;" ::: "memory");

    float m1 = -INFINITY, m2 = -INFINITY, l1 = 0.f, l2 = 0.f;
    float ao[8][4];
#pragma unroll
    for (int nf = 0; nf < 8; nf++)
#pragma unroll
        for (int j = 0; j < 4; j++) ao[nf][j] = 0.f;
    uint32_t qh[4][4], qlo[4][4];
    int qloaded = 0;

    for (int t = 0; t < 16; ++t) {
        if (t + 1 < 16) {
            load_kv(t + 1, (t + 1) & 1);
            asm volatile("cp.async.commit_group;" ::: "memory");
            asm volatile("cp.async.wait_group 1;" ::: "memory");
        } else {
            asm volatile("cp.async.wait_group 0;" ::: "memory");
        }
        __syncthreads();
        if (!qloaded) {
            qloaded = 1;
#pragma unroll
            for (int kc = 0; kc < 4; kc++) {
                int r = wid * 16 + (lane & 15), cg = kc * 2 + (lane >> 4);
                uint32_t sw = (uint32_t)(r * 128 + ((cg ^ (r & 7)) << 4));
                ldsm4(qh[kc],  sb + sw);
                ldsm4(qlo[kc], sb + 16384 + sw);
            }
        }
        const uint32_t kb = sb + 32768 + (uint32_t)(t & 1) * 65536;

        float sa[16][4];
#pragma unroll
        for (int ni = 0; ni < 16; ni++)
#pragma unroll
            for (int j = 0; j < 4; j++) sa[ni][j] = 0.f;
#pragma unroll
        for (int kc = 0; kc < 4; kc++) {
            uint32_t kh[16][2], kl[16][2];
#pragma unroll
            for (int bi = 0; bi < 8; bi++) {
                int r = bi * 16 + (lane & 15), cg = kc * 2 + (lane >> 4);
                uint32_t sw = (uint32_t)(r * 128 + ((cg ^ (r & 7)) << 4));
                uint32_t t4[4];
                ldsm4(t4, kb + sw);
                kh[bi*2][0]=t4[0]; kh[bi*2][1]=t4[2]; kh[bi*2+1][0]=t4[1]; kh[bi*2+1][1]=t4[3];
                ldsm4(t4, kb + 16384 + sw);
                kl[bi*2][0]=t4[0]; kl[bi*2][1]=t4[2]; kl[bi*2+1][0]=t4[1]; kl[bi*2+1][1]=t4[3];
            }
#pragma unroll
            for (int ni = 0; ni < 16; ni++) {
                mma16816(sa[ni], qh[kc],  kh[ni]);
                mma16816(sa[ni], qh[kc],  kl[ni]);
                mma16816(sa[ni], qlo[kc], kh[ni]);
            }
        }

        float mx1 = -INFINITY, mx2 = -INFINITY;
#pragma unroll
        for (int ni = 0; ni < 16; ni++) {
            mx1 = fmaxf(mx1, fmaxf(sa[ni][0], sa[ni][1]));
            mx2 = fmaxf(mx2, fmaxf(sa[ni][2], sa[ni][3]));
        }
        mx1 = fmaxf(mx1, __shfl_xor_sync(0xffffffffu, mx1, 1));
        mx1 = fmaxf(mx1, __shfl_xor_sync(0xffffffffu, mx1, 2));
        mx2 = fmaxf(mx2, __shfl_xor_sync(0xffffffffu, mx2, 1));
        mx2 = fmaxf(mx2, __shfl_xor_sync(0xffffffffu, mx2, 2));
        float nm1 = fmaxf(m1, mx1), nm2 = fmaxf(m2, mx2);
        float al1 = __expf(m1 - nm1), al2 = __expf(m2 - nm2);
        float s1 = 0.f, s2 = 0.f;
#pragma unroll
        for (int ni = 0; ni < 16; ni++) {
            sa[ni][0] = __expf(sa[ni][0] - nm1); s1 += sa[ni][0];
            sa[ni][1] = __expf(sa[ni][1] - nm1); s1 += sa[ni][1];
            sa[ni][2] = __expf(sa[ni][2] - nm2); s2 += sa[ni][2];
            sa[ni][3] = __expf(sa[ni][3] - nm2); s2 += sa[ni][3];
        }
        s1 += __shfl_xor_sync(0xffffffffu, s1, 1);
        s1 += __shfl_xor_sync(0xffffffffu, s1, 2);
        s2 += __shfl_xor_sync(0xffffffffu, s2, 1);
        s2 += __shfl_xor_sync(0xffffffffu, s2, 2);
        l1 = l1 * al1 + s1; l2 = l2 * al2 + s2;
        m1 = nm1; m2 = nm2;
#pragma unroll
        for (int nf = 0; nf < 8; nf++) {
            ao[nf][0] *= al1; ao[nf][1] *= al1;
            ao[nf][2] *= al2; ao[nf][3] *= al2;
        }

#pragma unroll
        for (int j = 0; j < 8; j++) {
            uint32_t ph[4], pl[4];
            packsplit(sa[2*j][0],   sa[2*j][1],   ph[0], pl[0]);
            packsplit(sa[2*j][2],   sa[2*j][3],   ph[1], pl[1]);
            packsplit(sa[2*j+1][0], sa[2*j+1][1], ph[2], pl[2]);
            packsplit(sa[2*j+1][2], sa[2*j+1][3], ph[3], pl[3]);
            uint32_t vh[8][2], vl[8][2];
#pragma unroll
            for (int q = 0; q < 4; q++) {
                int row = j * 16 + ((lane >> 3) & 1) * 8 + (lane & 7);
                int g   = q * 2 + (lane >> 4);
                uint32_t sw = (uint32_t)(row * 128 + ((g ^ (row & 7)) << 4));
                uint32_t t4[4];
                ldsm4t(t4, kb + 32768 + sw);
                vh[q*2][0]=t4[0]; vh[q*2][1]=t4[1]; vh[q*2+1][0]=t4[2]; vh[q*2+1][1]=t4[3];
                ldsm4t(t4, kb + 49152 + sw);
                vl[q*2][0]=t4[0]; vl[q*2][1]=t4[1]; vl[q*2+1][0]=t4[2]; vl[q*2+1][1]=t4[3];
            }
#pragma unroll
            for (int nf = 0; nf < 8; nf++) {
                mma16816(ao[nf], ph, vh[nf]);
                mma16816(ao[nf], pl, vh[nf]);
                mma16816(ao[nf], ph, vl[nf]);
            }
        }
        __syncthreads();
    }

    float il1 = 1.f / l1, il2 = 1.f / l2;
    int r1 = q0 + wid * 16 + (lane >> 2);
    int cb = 2 * (lane & 3);
    size_t b1 = ((size_t)((b * S_ + r1) * NH + h)) * RK;
    size_t b2 = ((size_t)((b * S_ + r1 + 8) * NH + h)) * RK;
#pragma unroll
    for (int nf = 0; nf < 8; nf++) {
        int c = nf * 8 + cb;
        __nv_bfloat16 hh, ll;
        bsplit(ao[nf][0] * il1, hh, ll); g_oc_h[b1 + c]     = hh; g_oc_l[b1 + c]     = ll;
        bsplit(ao[nf][1] * il1, hh, ll); g_oc_h[b1 + c + 1] = hh; g_oc_l[b1 + c + 1] = ll;
        bsplit(ao[nf][2] * il2, hh, ll); g_oc_h[b2 + c]     = hh; g_oc_l[b2 + c]     = ll;
        bsplit(ao[nf][3] * il2, hh, ll); g_oc_h[b2 + c + 1] = hh; g_oc_l[b2 + c + 1] = ll;
    }
}

// ===================== launch =====================
#define SYMF(p, s) cudaGetSymbolAddress((void**)&p, s)

extern "C" void kernel_launch(void* const* d_in, const int* in_sizes, int n_in,
                              void* d_out, int out_size)
{
    const float* hs  = (const float*)d_in[0];
    const int*   pos = (const int*)  d_in[1];
    const float* Wq  = (const float*)d_in[2];
    const float* Wk  = (const float*)d_in[3];
    const float* Wv  = (const float*)d_in[4];
    const float* Wkc = (const float*)d_in[5];
    const float* Wvc = (const float*)d_in[6];
    const float* Wqa = (const float*)d_in[7];
    const float* Wqg = (const float*)d_in[8];
    const float* Wov = (const float*)d_in[9];
    const float* Wo  = (const float*)d_in[10];
    float* out = (float*)d_out;

    __nv_bfloat16 *hsh,*hsl,*woh,*wol,*ovh,*ovl,*och,*ocl,*gth,*gtl;
    SYMF(hsh,g_hs_h);  SYMF(hsl,g_hs_l);
    SYMF(woh,g_WoT_h); SYMF(wol,g_WoT_l);
    SYMF(ovh,g_WovT_h);SYMF(ovl,g_WovT_l);
    SYMF(och,g_oc_h);  SYMF(ocl,g_oc_l);
    SYMF(gth,g_gat_h); SYMF(gtl,g_gat_l);

    prep_misc<<<256, 256>>>(pos, Wqa, Wqg, Wkc, Wov);                     // 1
    split2<<<4096, 256>>>(hs, hsh, hsl, BS_ROWS*HID);                     // 2
    cudaFuncSetAttribute(prep_weights, cudaFuncAttributeMaxDynamicSharedMemorySize, PREPW_SMEM);
    prep_weights<<<12800, 256, PREPW_SMEM>>>(Wq, Wk, Wo, Wv, Wvc);        // 3

    cudaFuncSetAttribute(gemm_one,   cudaFuncAttributeMaxDynamicSharedMemorySize, GSMEM);
    cudaFuncSetAttribute(gemm_qkv,   cudaFuncAttributeMaxDynamicSharedMemorySize, GSMEM);
    cudaFuncSetAttribute(gemm_heads, cudaFuncAttributeMaxDynamicSharedMemorySize, GSMEM);

    gemm_qkv<<<dim3(32,8,3), NTHR, GSMEM>>>(hsh, hsl);                    // 4 (profiled)

    gemm_heads<<<dim3(512,1,2), NTHR, GSMEM>>>();                         // 5

    cudaFuncSetAttribute(attn_mma, cudaFuncAttributeMaxDynamicSharedMemorySize, ATT_SMEM);
    attn_mma<<<dim3(S_/128, B_*NH), 256, ATT_SMEM>>>();                   // 6

    gemm_one<<<dim3(512,1), NTHR, GSMEM>>>(och, ocl, ovh, ovl, 64, 4, 128, 128,
                                           nullptr, gth, gtl);            // 7
    gemm_one<<<dim3(32,8), NTHR, GSMEM>>>(gth, gtl, woh, wol, HID, 0, HID, HID,
                                          out, nullptr, nullptr);         // 8
}

// round 16
// speedup vs baseline: 1.1202x; 1.1202x over previous
#include <cuda_runtime.h>
#include <cuda_bf16.h>
#include <math.h>
#include <stdint.h>

#define B_   2
#define S_   2048
#define HID  2048
#define NH   16
#define HD   128
#define RK   64
#define BS_ROWS (B_*S_)        // 4096
#define HROWS   (B_*S_*NH)     // 65536

// ===================== scratch (static __device__) =====================
__device__ __nv_bfloat16 g_hs_h[BS_ROWS*HID],  g_hs_l[BS_ROWS*HID];
__device__ __nv_bfloat16 g_WqT_h[HID*HID], g_WqT_l[HID*HID];
__device__ __nv_bfloat16 g_WkT_h[HID*HID], g_WkT_l[HID*HID];
__device__ __nv_bfloat16 g_WoT_h[HID*HID], g_WoT_l[HID*HID];
__device__ __nv_bfloat16 g_MvT_h[1024*HID], g_MvT_l[1024*HID];   // folded (Wv·Wvc)^T
__device__ __nv_bfloat16 g_Wcat_h[256*HD], g_Wcat_l[256*HD];   // [Wqa|Wqg]^T padded
__device__ __nv_bfloat16 g_WkcT_h[256*HD], g_WkcT_l[256*HD];
__device__ __nv_bfloat16 g_WovT_h[256*RK], g_WovT_l[256*RK];
__device__ __nv_bfloat16 g_qa_h[HROWS*RK], g_qa_l[HROWS*RK];   // pre-scaled 1/8
__device__ __nv_bfloat16 g_kc_h[HROWS*RK], g_kc_l[HROWS*RK];
__device__ __nv_bfloat16 g_vc_h[HROWS*RK], g_vc_l[HROWS*RK];
__device__ float g_qg[HROWS*HD];
__device__ __nv_bfloat16 g_oc_h[HROWS*RK], g_oc_l[HROWS*RK];
__device__ __nv_bfloat16 g_gat_h[BS_ROWS*HID], g_gat_l[BS_ROWS*HID];
__device__ float g_cos[S_*32], g_sin[S_*32];

// ===================== PTX helpers =====================
__device__ __forceinline__ uint32_t smem_u32(const void* p) {
    uint32_t a;
    asm("{ .reg .u64 t; cvta.to.shared.u64 t, %1; cvt.u32.u64 %0, t; }" : "=r"(a) : "l"(p));
    return a;
}
__device__ __forceinline__ void cpasync16(uint32_t dst, const void* src) {
    asm volatile("cp.async.cg.shared.global [%0], [%1], 16;" :: "r"(dst), "l"(src));
}
__device__ __forceinline__ void ldsm4(uint32_t* r, uint32_t addr) {
    asm volatile("ldmatrix.sync.aligned.m8n8.x4.shared.b16 {%0,%1,%2,%3}, [%4];"
        : "=r"(r[0]), "=r"(r[1]), "=r"(r[2]), "=r"(r[3]) : "r"(addr));
}
__device__ __forceinline__ void ldsm4t(uint32_t* r, uint32_t addr) {
    asm volatile("ldmatrix.sync.aligned.m8n8.x4.trans.shared.b16 {%0,%1,%2,%3}, [%4];"
        : "=r"(r[0]), "=r"(r[1]), "=r"(r[2]), "=r"(r[3]) : "r"(addr));
}
__device__ __forceinline__ void mma16816(float* c, const uint32_t* a, const uint32_t* b) {
    asm volatile(
        "mma.sync.aligned.m16n8k16.row.col.f32.bf16.bf16.f32 "
        "{%0,%1,%2,%3}, {%4,%5,%6,%7}, {%8,%9}, {%0,%1,%2,%3};"
        : "+f"(c[0]), "+f"(c[1]), "+f"(c[2]), "+f"(c[3])
        : "r"(a[0]), "r"(a[1]), "r"(a[2]), "r"(a[3]), "r"(b[0]), "r"(b[1]));
}
__device__ __forceinline__ void bsplit(float v, __nv_bfloat16& h, __nv_bfloat16& l) {
    h = __float2bfloat16(v);
    l = __float2bfloat16(v - __bfloat162float(h));
}
__device__ __forceinline__ void packsplit(float lo, float hi, uint32_t& ph, uint32_t& pl) {
    __nv_bfloat16 hl = __float2bfloat16(lo), hh = __float2bfloat16(hi);
    ph = (uint32_t)__bfloat16_as_ushort(hl) | ((uint32_t)__bfloat16_as_ushort(hh) << 16);
    __nv_bfloat16 ll = __float2bfloat16(lo - __bfloat162float(hl));
    __nv_bfloat16 lh = __float2bfloat16(hi - __bfloat162float(hh));
    pl = (uint32_t)__bfloat16_as_ushort(ll) | ((uint32_t)__bfloat16_as_ushort(lh) << 16);
}

// ===================== unified prep kernel =====================
// grid slices: [0,12288) transpose Wq/Wk/Wo; [12288,12800) fold_v;
// [12800,16896) split hs; [16896,17152) trig + small weights
#define PREPW_SMEM 66560
__global__ void prep_all(const float* __restrict__ hs, const int* __restrict__ pos,
                         const float* __restrict__ Wq, const float* __restrict__ Wk,
                         const float* __restrict__ Wv, const float* __restrict__ Wvc,
                         const float* __restrict__ Wqa, const float* __restrict__ Wqg,
                         const float* __restrict__ Wkc, const float* __restrict__ Wov,
                         const float* __restrict__ Wo) {
    extern __shared__ float fsm[];
    const int gid = blockIdx.x;
    const int t = threadIdx.x;
    if (gid < 12288) {
        int z = gid >> 12, rem = gid & 4095;
        int bx = rem & 63, by = rem >> 6;
        const float* in = (z == 0) ? Wq : (z == 1) ? Wk : Wo;
        __nv_bfloat16* dh = (z == 0) ? g_WqT_h : (z == 1) ? g_WkT_h : g_WoT_h;
        __nv_bfloat16* dl = (z == 0) ? g_WqT_l : (z == 1) ? g_WkT_l : g_WoT_l;
        float (*tt)[33] = (float(*)[33])fsm;
        int x = t & 31, y = t >> 5;
        int bc = bx * 32, br = by * 32;
#pragma unroll
        for (int j = 0; j < 32; j += 8)
            tt[y + j][x] = in[(size_t)(br + y + j) * HID + bc + x];
        __syncthreads();
#pragma unroll
        for (int j = 0; j < 32; j += 8) {
            float v = tt[x][y + j];
            __nv_bfloat16 h, l; bsplit(v, h, l);
            size_t o = (size_t)(bc + y + j) * HID + br + x;
            dh[o] = h; dl[o] = l;
        }
    } else if (gid < 12800) {
        int fid = gid - 12288;
        int e0 = (fid & 31) * 64, h = fid >> 5;
        float* sWv = fsm;
        float* sVc = fsm + 8192;
        for (int i = t; i < 8192; i += 256) {
            int e = i >> 7, d = i & 127;
            sWv[i] = Wv[(size_t)(e0 + e) * HID + h * HD + d];
        }
        for (int i = t; i < 8192; i += 256) {
            int r = i & 63, d = i >> 6;
            sVc[r * 132 + d] = Wvc[d * 64 + r];
        }
        __syncthreads();
        const int r = t & 63, eg = t >> 6;
        float acc[16];
#pragma unroll
        for (int ei = 0; ei < 16; ei++) acc[ei] = 0.f;
        for (int d = 0; d < 128; d += 4) {
            float4 v4 = *(float4*)&sVc[r * 132 + d];
#pragma unroll
            for (int ei = 0; ei < 16; ei++) {
                float4 w4 = *(float4*)&sWv[(eg * 16 + ei) * 128 + d];
                acc[ei] += w4.x * v4.x + w4.y * v4.y + w4.z * v4.z + w4.w * v4.w;
            }
        }
        size_t base = (size_t)(h * 64 + r) * HID + e0 + eg * 16;
#pragma unroll
        for (int ei = 0; ei < 16; ei++) {
            __nv_bfloat16 hh, ll; bsplit(acc[ei], hh, ll);
            g_MvT_h[base + ei] = hh; g_MvT_l[base + ei] = ll;
        }
    } else if (gid < 16896) {
        size_t base = (size_t)(gid - 12800) * 2048;
#pragma unroll
        for (int j = 0; j < 8; j++) {
            size_t i = base + t + j * 256;
            __nv_bfloat16 h, l; bsplit(hs[i], h, l);
            g_hs_h[i] = h; g_hs_l[i] = l;
        }
    } else {
        int idx = (gid - 16896) * 256 + t;
        if (idx < S_ * 32) {
            int s = idx >> 5, i = idx & 31;
            float p = (float)pos[s];
            float inv = 1.0f / powf(10000.0f, (float)(2 * i) * (1.0f / 64.0f));
            float a = p * inv;
            g_cos[idx] = cosf(a);
            g_sin[idx] = sinf(a);
        }
        if (idx < 32768) {                 // cat: 256 rows x 128
            int n = idx >> 7, k = idx & 127;
            float v = (n < 64) ? Wqa[k * 64 + n] : (n < 192) ? Wqg[k * 128 + (n - 64)] : 0.f;
            __nv_bfloat16 h, l; bsplit(v, h, l);
            g_Wcat_h[idx] = h; g_Wcat_l[idx] = l;
        } else if (idx < 49152) {          // kc: rows 0..127
            int i2 = idx - 32768;
            int n = i2 >> 7, k = i2 & 127;
            float v = (n < 64) ? Wkc[k * 64 + n] : 0.f;
            __nv_bfloat16 h, l; bsplit(v, h, l);
            g_WkcT_h[i2] = h; g_WkcT_l[i2] = l;
        } else if (idx < 57344) {          // ov: rows 0..127
            int i2 = idx - 49152;
            int n = i2 >> 6, k = i2 & 63;
            __nv_bfloat16 h, l; bsplit(Wov[k * 128 + n], h, l);
            g_WovT_h[i2] = h; g_WovT_l[i2] = l;
        }
    }
}

__global__ void knop() {}

// ===================== split-bf16 warp-MMA GEMM (512 thr, 16 warps) ======
// 4x4 warp grid, 32x32 warp tiles, KC=64, 3-stage cp.async.
#define NTHR    512
#define STAGE_B 65536
#define GSMEM   (3 * STAGE_B)
#define SQ_OFF  69632
#define WB_OFF  135168

__device__ __forceinline__ void mainloop_sC(
    const __nv_bfloat16* __restrict__ Ah, const __nv_bfloat16* __restrict__ Al,
    const __nv_bfloat16* __restrict__ Bh, const __nv_bfloat16* __restrict__ Bl,
    int Kdim, char* smem, int row0, int n0)
{
    const uint32_t sb = smem_u32(smem);
    const int tid  = threadIdx.x;
    const int wid  = tid >> 5, lane = tid & 31;
    const int wm   = wid >> 2, wn = wid & 3;

    float acc[2][4][4];
#pragma unroll
    for (int mi = 0; mi < 2; mi++)
#pragma unroll
        for (int ni = 0; ni < 4; ni++)
#pragma unroll
            for (int j = 0; j < 4; j++) acc[mi][ni][j] = 0.f;

    const int NIT = Kdim >> 6;

    auto load_chunk = [&](int it, int s) {
        const int kc0 = it << 6;
        const uint32_t base = sb + (uint32_t)s * STAGE_B;
#pragma unroll
        for (int q = 0; q < 2; q++) {
            int g = tid + q * NTHR;
            int r = g >> 3, cg = g & 7;
            uint32_t sw = (uint32_t)(r * 128 + ((cg ^ (r & 7)) << 4));
            size_t ga = (size_t)(row0 + r) * Kdim + kc0 + cg * 8;
            size_t gb = (size_t)(n0   + r) * Kdim + kc0 + cg * 8;
            cpasync16(base +         sw, Ah + ga);
            cpasync16(base + 16384 + sw, Al + ga);
            cpasync16(base + 32768 + sw, Bh + gb);
            cpasync16(base + 49152 + sw, Bl + gb);
        }
        asm volatile("cp.async.commit_group;" ::: "memory");
    };

    auto compute = [&](int s) {
        const uint32_t aB = sb + (uint32_t)s * STAGE_B;
        const uint32_t bB = aB + 32768;
#pragma unroll
        for (int ks = 0; ks < 4; ks++) {
            uint32_t ahf[2][4], alf[2][4], bhf[4][2], blf[4][2];
#pragma unroll
            for (int mi = 0; mi < 2; mi++) {
                int r  = wm * 32 + mi * 16 + (lane & 15);
                int cg = ks * 2 + (lane >> 4);
                uint32_t sw = (uint32_t)(r * 128 + ((cg ^ (r & 7)) << 4));
                ldsm4(ahf[mi], aB + sw);
                ldsm4(alf[mi], aB + 16384 + sw);
            }
#pragma unroll
            for (int bi = 0; bi < 2; bi++) {
                int r  = wn * 32 + bi * 16 + (lane & 15);
                int cg = ks * 2 + (lane >> 4);
                uint32_t sw = (uint32_t)(r * 128 + ((cg ^ (r & 7)) << 4));
                uint32_t t[4];
                ldsm4(t, bB + sw);
                bhf[bi*2][0]   = t[0]; bhf[bi*2][1]   = t[2];
                bhf[bi*2+1][0] = t[1]; bhf[bi*2+1][1] = t[3];
                ldsm4(t, bB + 16384 + sw);
                blf[bi*2][0]   = t[0]; blf[bi*2][1]   = t[2];
                blf[bi*2+1][0] = t[1]; blf[bi*2+1][1] = t[3];
            }
#pragma unroll
            for (int mi = 0; mi < 2; mi++)
#pragma unroll
                for (int ni = 0; ni < 4; ni++) {
                    mma16816(acc[mi][ni], ahf[mi], bhf[ni]);
                    mma16816(acc[mi][ni], ahf[mi], blf[ni]);
                    mma16816(acc[mi][ni], alf[mi], bhf[ni]);
                }
        }
    };

    load_chunk(0, 0);
    int stage = 0;
    for (int it = 0; it < NIT; ++it) {
        if (it + 1 < NIT) {
            int ns = stage + 1; if (ns == 3) ns = 0;
            load_chunk(it + 1, ns);
            asm volatile("cp.async.wait_group 1;" ::: "memory");
        } else {
            asm volatile("cp.async.wait_group 0;" ::: "memory");
        }
        __syncthreads();
        compute(stage);
        if (++stage == 3) stage = 0;
    }
    __syncthreads();

    float* sC = (float*)smem;
#pragma unroll
    for (int mi = 0; mi < 2; mi++)
#pragma unroll
        for (int ni = 0; ni < 4; ni++) {
            int m0 = wm * 32 + mi * 16 + (lane >> 2);
            int c0 = wn * 32 + ni * 8 + (lane & 3) * 2;
            sC[m0 * 132 + c0]           = acc[mi][ni][0];
            sC[m0 * 132 + c0 + 1]       = acc[mi][ni][1];
            sC[(m0 + 8) * 132 + c0]     = acc[mi][ni][2];
            sC[(m0 + 8) * 132 + c0 + 1] = acc[mi][ni][3];
        }
    __syncthreads();
}

// simple epilogues over sC. mode 0: fp32 out; 1: split; 4: silu(qg)*v split
__device__ __forceinline__ void epilogue_simple(
    int mode, int Nvalid, int ostride,
    float* __restrict__ outf, __nv_bfloat16* __restrict__ oh, __nv_bfloat16* __restrict__ ol,
    char* smem, int row0, int n0)
{
    float* sC = (float*)smem;
    const int tid = threadIdx.x;
    for (int x = tid; x < 128 * 128; x += NTHR) {
        int r = x >> 7, c = x & 127;
        int gr = row0 + r, gc = n0 + c;
        if (gc >= Nvalid) continue;
        float v = sC[r * 132 + c];
        if (mode == 0) {
            outf[(size_t)gr * ostride + gc] = v;
        } else if (mode == 1) {
            __nv_bfloat16 h, l; bsplit(v, h, l);
            size_t o = (size_t)gr * ostride + gc; oh[o] = h; ol[o] = l;
        } else { // 4
            float g = g_qg[(size_t)gr * 128 + gc];
            float sil = g / (1.0f + expf(-g));
            __nv_bfloat16 h, l; bsplit(sil * v, h, l);
            size_t o = (size_t)gr * 128 + gc; oh[o] = h; ol[o] = l;
        }
    }
}

// ===== fused head-projection epilogue (512 thr) =====
template<int R, bool IS_Q>
__device__ __forceinline__ void head_epilogue(
    const __nv_bfloat16* __restrict__ Wh, const __nv_bfloat16* __restrict__ Wl,
    char* smem, int row0, int h)
{
    const uint32_t sb = smem_u32(smem);
    float* sC = (float*)smem;
    const int tid = threadIdx.x, wid = tid >> 5, lane = tid & 31;
    const int wm = wid >> 2, wn = wid & 3;
    constexpr int NB = R / 32;

    for (int i = tid; i < R * 8; i += NTHR) {
        int r = i >> 3, cg = i & 7;
        uint32_t sw = (uint32_t)(r * 128 + ((cg ^ (r & 7)) << 4));
        cpasync16(sb + WB_OFF + sw,           Wh + (size_t)r * 128 + cg * 8);
        cpasync16(sb + WB_OFF + R * 128 + sw, Wl + (size_t)r * 128 + cg * 8);
    }
    asm volatile("cp.async.commit_group;" ::: "memory");

    for (int x = tid; x < 128 * 128; x += NTHR) {
        int r = x >> 7, d = x & 127;
        float v = sC[r * 132 + d];
        if (d < 64) {
            int i = d & 31;
            int sdx = ((row0 + r) & (S_ - 1)) * 32 + i;
            float co = g_cos[sdx], si = g_sin[sdx];
            float p = (d < 32) ? sC[r * 132 + d + 32] : sC[r * 132 + d - 32];
            v = (d < 32) ? v * co - p * si : v * co + p * si;
        }
        __nv_bfloat16 hh, ll; bsplit(v, hh, ll);
        int kc = d >> 6, dd = d & 63;
        uint32_t off = (uint32_t)(r * 128 + (((dd >> 3) ^ (r & 7)) << 4) + (dd & 7) * 2);
        *(__nv_bfloat16*)(smem + SQ_OFF + kc * 32768 + off)         = hh;
        *(__nv_bfloat16*)(smem + SQ_OFF + kc * 32768 + 16384 + off) = ll;
    }
    __syncthreads();

    for (int i = tid; i < R * 8; i += NTHR) {
        int r = i >> 3, cg = i & 7;
        uint32_t sw = (uint32_t)(r * 128 + ((cg ^ (r & 7)) << 4));
        cpasync16(sb + sw,           Wh + (size_t)r * 128 + 64 + cg * 8);
        cpasync16(sb + R * 128 + sw, Wl + (size_t)r * 128 + 64 + cg * 8);
    }
    asm volatile("cp.async.commit_group;" ::: "memory");
    asm volatile("cp.async.wait_group 1;" ::: "memory");
    __syncthreads();

    float acc2[2][NB][4];
#pragma unroll
    for (int mi = 0; mi < 2; mi++)
#pragma unroll
        for (int ni = 0; ni < NB; ni++)
#pragma unroll
            for (int j = 0; j < 4; j++) acc2[mi][ni][j] = 0.f;

#pragma unroll
    for (int kc = 0; kc < 2; kc++) {
        if (kc == 1) {
            asm volatile("cp.async.wait_group 0;" ::: "memory");
            __syncthreads();
        }
        const uint32_t aB = sb + SQ_OFF + kc * 32768;
        const uint32_t bB = (kc == 0) ? sb + WB_OFF : sb;
        const uint32_t bL = bB + R * 128;
#pragma unroll
        for (int ks = 0; ks < 4; ks++) {
            uint32_t ahf[2][4], alf[2][4], bhf[NB][2], blf[NB][2];
#pragma unroll
            for (int mi = 0; mi < 2; mi++) {
                int r  = wm * 32 + mi * 16 + (lane & 15);
                int cg = ks * 2 + (lane >> 4);
                uint32_t sw = (uint32_t)(r * 128 + ((cg ^ (r & 7)) << 4));
                ldsm4(ahf[mi], aB + sw);
                ldsm4(alf[mi], aB + 16384 + sw);
            }
#pragma unroll
            for (int bi = 0; bi < NB / 2; bi++) {
                int r  = wn * (R / 4) + bi * 16 + (lane & 15);
                int cg = ks * 2 + (lane >> 4);
                uint32_t sw = (uint32_t)(r * 128 + ((cg ^ (r & 7)) << 4));
                uint32_t t4[4];
                ldsm4(t4, bB + sw);
                bhf[bi*2][0]   = t4[0]; bhf[bi*2][1]   = t4[2];
                bhf[bi*2+1][0] = t4[1]; bhf[bi*2+1][1] = t4[3];
                ldsm4(t4, bL + sw);
                blf[bi*2][0]   = t4[0]; blf[bi*2][1]   = t4[2];
                blf[bi*2+1][0] = t4[1]; blf[bi*2+1][1] = t4[3];
            }
#pragma unroll
            for (int mi = 0; mi < 2; mi++)
#pragma unroll
                for (int ni = 0; ni < NB; ni++) {
                    mma16816(acc2[mi][ni], ahf[mi], bhf[ni]);
                    mma16816(acc2[mi][ni], ahf[mi], blf[ni]);
                    mma16816(acc2[mi][ni], alf[mi], bhf[ni]);
                }
        }
    }

#pragma unroll
    for (int mi = 0; mi < 2; mi++)
#pragma unroll
        for (int ni = 0; ni < NB; ni++) {
            int gr = row0 + wm * 32 + mi * 16 + (lane >> 2);
            int c  = wn * (R / 4) + ni * 8 + (lane & 3) * 2;
#pragma unroll
            for (int half = 0; half < 2; half++) {
                int grr = gr + half * 8;
                float v0 = acc2[mi][ni][half * 2], v1 = acc2[mi][ni][half * 2 + 1];
                size_t hr = (size_t)grr * NH + h;
                if (IS_Q) {
                    if (c < 64) {
                        __nv_bfloat16 hh, ll;
                        bsplit(v0 * 0.125f, hh, ll);
                        g_qa_h[hr * 64 + c] = hh;     g_qa_l[hr * 64 + c] = ll;
                        bsplit(v1 * 0.125f, hh, ll);
                        g_qa_h[hr * 64 + c + 1] = hh; g_qa_l[hr * 64 + c + 1] = ll;
                    } else {
                        g_qg[hr * 128 + (c - 64)]     = v0;
                        g_qg[hr * 128 + (c - 63)]     = v1;
                    }
                } else {
                    __nv_bfloat16 hh, ll;
                    bsplit(v0, hh, ll);
                    g_kc_h[hr * 64 + c] = hh;     g_kc_l[hr * 64 + c] = ll;
                    bsplit(v1, hh, ll);
                    g_kc_h[hr * 64 + c + 1] = hh; g_kc_l[hr * 64 + c + 1] = ll;
                }
            }
        }
}

__global__ __launch_bounds__(NTHR) void gemm_one(
    const __nv_bfloat16* Ah, const __nv_bfloat16* Al,
    const __nv_bfloat16* Bh, const __nv_bfloat16* Bl,
    int Kdim, int mode, int Nvalid, int ostride,
    float* outf, __nv_bfloat16* oh, __nv_bfloat16* ol)
{
    extern __shared__ __align__(128) char smem[];
    const int r0 = blockIdx.x * 128, c0 = blockIdx.y * 128;
    mainloop_sC(Ah, Al, Bh, Bl, Kdim, smem, r0, c0);
    epilogue_simple(mode, Nvalid, ostride, outf, oh, ol, smem, r0, c0);
}

// Q (rope + fused qa|qg), K (rope + fused kc), V-folded (split vc): grid (32,16,3)
__global__ __launch_bounds__(NTHR) void gemm_qkv(
    const __nv_bfloat16* Ah, const __nv_bfloat16* Al)
{
    extern __shared__ __align__(128) char smem[];
    const int r0 = blockIdx.x * 128, c0 = blockIdx.y * 128;
    const int z = blockIdx.z;
    if (z == 2 && blockIdx.y >= 8) return;
    const __nv_bfloat16* Bh = (z == 0) ? g_WqT_h : (z == 1) ? g_WkT_h : g_MvT_h;
    const __nv_bfloat16* Bl = (z == 0) ? g_WqT_l : (z == 1) ? g_WkT_l : g_MvT_l;
    mainloop_sC(Ah, Al, Bh, Bl, HID, smem, r0, c0);
    if (z == 0)      head_epilogue<192, true >(g_Wcat_h, g_Wcat_l, smem, r0, blockIdx.y);
    else if (z == 1) head_epilogue<64,  false>(g_WkcT_h, g_WkcT_l, smem, r0, blockIdx.y);
    else             epilogue_simple(1, 1024, 1024, nullptr, g_vc_h, g_vc_l, smem, r0, c0);
}

// ===================== tensor-core flash attention (unchanged) ===========
#define ATT_SMEM (32768 + 2 * 65536)

__global__ __launch_bounds__(256, 1) void attn_mma()
{
    extern __shared__ __align__(128) char smem[];
    const uint32_t sb = smem_u32(smem);
    const int tid = threadIdx.x, wid = tid >> 5, lane = tid & 31;
    const int b = blockIdx.y >> 4, h = blockIdx.y & 15;
    const int q0 = blockIdx.x * 128;

    for (int i = tid; i < 1024; i += 256) {
        int r = i >> 3, g = i & 7;
        uint32_t sw = (uint32_t)(r * 128 + ((g ^ (r & 7)) << 4));
        size_t gl = ((size_t)((b * S_ + q0 + r) * NH + h)) * RK + g * 8;
        cpasync16(sb + sw,         g_qa_h + gl);
        cpasync16(sb + 16384 + sw, g_qa_l + gl);
    }
    auto load_kv = [&](int t, int s) {
        const uint32_t kb = sb + 32768 + (uint32_t)s * 65536;
        for (int i = tid; i < 1024; i += 256) {
            int r = i >> 3, g = i & 7;
            uint32_t sw = (uint32_t)(r * 128 + ((g ^ (r & 7)) << 4));
            size_t gl = ((size_t)((b * S_ + t * 128 + r) * NH + h)) * RK + g * 8;
            cpasync16(kb + sw,         g_kc_h + gl);
            cpasync16(kb + 16384 + sw, g_kc_l + gl);
            cpasync16(kb + 32768 + sw, g_vc_h + gl);
            cpasync16(kb + 49152 + sw, g_vc_l + gl);
        }
    };
    load_kv(0, 0);
    asm volatile("cp.async.commit_group;" ::: "memory");

    float m1 = -INFINITY, m2 = -INFINITY, l1 = 0.f, l2 = 0.f;
    float ao[8][4];
#pragma unroll
    for (int nf = 0; nf < 8; nf++)
#pragma unroll
        for (int j = 0; j < 4; j++) ao[nf][j] = 0.f;
    uint32_t qh[4][4], qlo[4][4];
    int qloaded = 0;

    for (int t = 0; t < 16; ++t) {
        if (t + 1 < 16) {
            load_kv(t + 1, (t + 1) & 1);
            asm volatile("cp.async.commit_group;" ::: "memory");
            asm volatile("cp.async.wait_group 1;" ::: "memory");
        } else {
            asm volatile("cp.async.wait_group 0;" ::: "memory");
        }
        __syncthreads();
        if (!qloaded) {
            qloaded = 1;
#pragma unroll
            for (int kc = 0; kc < 4; kc++) {
                int r = wid * 16 + (lane & 15), cg = kc * 2 + (lane >> 4);
                uint32_t sw = (uint32_t)(r * 128 + ((cg ^ (r & 7)) << 4));
                ldsm4(qh[kc],  sb + sw);
                ldsm4(qlo[kc], sb + 16384 + sw);
            }
        }
        const uint32_t kb = sb + 32768 + (uint32_t)(t & 1) * 65536;

        float sa[16][4];
#pragma unroll
        for (int ni = 0; ni < 16; ni++)
#pragma unroll
            for (int j = 0; j < 4; j++) sa[ni][j] = 0.f;
#pragma unroll
        for (int kc = 0; kc < 4; kc++) {
            uint32_t kh[16][2], kl[16][2];
#pragma unroll
            for (int bi = 0; bi < 8; bi++) {
                int r = bi * 16 + (lane & 15), cg = kc * 2 + (lane >> 4);
                uint32_t sw = (uint32_t)(r * 128 + ((cg ^ (r & 7)) << 4));
                uint32_t t4[4];
                ldsm4(t4, kb + sw);
                kh[bi*2][0]=t4[0]; kh[bi*2][1]=t4[2]; kh[bi*2+1][0]=t4[1]; kh[bi*2+1][1]=t4[3];
                ldsm4(t4, kb + 16384 + sw);
                kl[bi*2][0]=t4[0]; kl[bi*2][1]=t4[2]; kl[bi*2+1][0]=t4[1]; kl[bi*2+1][1]=t4[3];
            }
#pragma unroll
            for (int ni = 0; ni < 16; ni++) {
                mma16816(sa[ni], qh[kc],  kh[ni]);
                mma16816(sa[ni], qh[kc],  kl[ni]);
                mma16816(sa[ni], qlo[kc], kh[ni]);
            }
        }

        float mx1 = -INFINITY, mx2 = -INFINITY;
#pragma unroll
        for (int ni = 0; ni < 16; ni++) {
            mx1 = fmaxf(mx1, fmaxf(sa[ni][0], sa[ni][1]));
            mx2 = fmaxf(mx2, fmaxf(sa[ni][2], sa[ni][3]));
        }
        mx1 = fmaxf(mx1, __shfl_xor_sync(0xffffffffu, mx1, 1));
        mx1 = fmaxf(mx1, __shfl_xor_sync(0xffffffffu, mx1, 2));
        mx2 = fmaxf(mx2, __shfl_xor_sync(0xffffffffu, mx2, 1));
        mx2 = fmaxf(mx2, __shfl_xor_sync(0xffffffffu, mx2, 2));
        float nm1 = fmaxf(m1, mx1), nm2 = fmaxf(m2, mx2);
        float al1 = __expf(m1 - nm1), al2 = __expf(m2 - nm2);
        float s1 = 0.f, s2 = 0.f;
#pragma unroll
        for (int ni = 0; ni < 16; ni++) {
            sa[ni][0] = __expf(sa[ni][0] - nm1); s1 += sa[ni][0];
            sa[ni][1] = __expf(sa[ni][1] - nm1); s1 += sa[ni][1];
            sa[ni][2] = __expf(sa[ni][2] - nm2); s2 += sa[ni][2];
            sa[ni][3] = __expf(sa[ni][3] - nm2); s2 += sa[ni][3];
        }
        s1 += __shfl_xor_sync(0xffffffffu, s1, 1);
        s1 += __shfl_xor_sync(0xffffffffu, s1, 2);
        s2 += __shfl_xor_sync(0xffffffffu, s2, 1);
        s2 += __shfl_xor_sync(0xffffffffu, s2, 2);
        l1 = l1 * al1 + s1; l2 = l2 * al2 + s2;
        m1 = nm1; m2 = nm2;
#pragma unroll
        for (int nf = 0; nf < 8; nf++) {
            ao[nf][0] *= al1; ao[nf][1] *= al1;
            ao[nf][2] *= al2; ao[nf][3] *= al2;
        }

#pragma unroll
        for (int j = 0; j < 8; j++) {
            uint32_t ph[4], pl[4];
            packsplit(sa[2*j][0],   sa[2*j][1],   ph[0], pl[0]);
            packsplit(sa[2*j][2],   sa[2*j][3],   ph[1], pl[1]);
            packsplit(sa[2*j+1][0], sa[2*j+1][1], ph[2], pl[2]);
            packsplit(sa[2*j+1][2], sa[2*j+1][3], ph[3], pl[3]);
            uint32_t vh[8][2], vl[8][2];
#pragma unroll
            for (int q = 0; q < 4; q++) {
                int row = j * 16 + ((lane >> 3) & 1) * 8 + (lane & 7);
                int g   = q * 2 + (lane >> 4);
                uint32_t sw = (uint32_t)(row * 128 + ((g ^ (row & 7)) << 4));
                uint32_t t4[4];
                ldsm4t(t4, kb + 32768 + sw);
                vh[q*2][0]=t4[0]; vh[q*2][1]=t4[1]; vh[q*2+1][0]=t4[2]; vh[q*2+1][1]=t4[3];
                ldsm4t(t4, kb + 49152 + sw);
                vl[q*2][0]=t4[0]; vl[q*2][1]=t4[1]; vl[q*2+1][0]=t4[2]; vl[q*2+1][1]=t4[3];
            }
#pragma unroll
            for (int nf = 0; nf < 8; nf++) {
                mma16816(ao[nf], ph, vh[nf]);
                mma16816(ao[nf], pl, vh[nf]);
                mma16816(ao[nf], ph, vl[nf]);
            }
        }
        __syncthreads();
    }

    float il1 = 1.f / l1, il2 = 1.f / l2;
    int r1 = q0 + wid * 16 + (lane >> 2);
    int cb = 2 * (lane & 3);
    size_t b1 = ((size_t)((b * S_ + r1) * NH + h)) * RK;
    size_t b2 = ((size_t)((b * S_ + r1 + 8) * NH + h)) * RK;
#pragma unroll
    for (int nf = 0; nf < 8; nf++) {
        int c = nf * 8 + cb;
        __nv_bfloat16 hh, ll;
        bsplit(ao[nf][0] * il1, hh, ll); g_oc_h[b1 + c]     = hh; g_oc_l[b1 + c]     = ll;
        bsplit(ao[nf][1] * il1, hh, ll); g_oc_h[b1 + c + 1] = hh; g_oc_l[b1 + c + 1] = ll;
        bsplit(ao[nf][2] * il2, hh, ll); g_oc_h[b2 + c]     = hh; g_oc_l[b2 + c]     = ll;
        bsplit(ao[nf][3] * il2, hh, ll); g_oc_h[b2 + c + 1] = hh; g_oc_l[b2 + c + 1] = ll;
    }
}

// ===================== launch =====================
#define SYMF(p, s) cudaGetSymbolAddress((void**)&p, s)

extern "C" void kernel_launch(void* const* d_in, const int* in_sizes, int n_in,
                              void* d_out, int out_size)
{
    const float* hs  = (const float*)d_in[0];
    const int*   pos = (const int*)  d_in[1];
    const float* Wq  = (const float*)d_in[2];
    const float* Wk  = (const float*)d_in[3];
    const float* Wv  = (const float*)d_in[4];
    const float* Wkc = (const float*)d_in[5];
    const float* Wvc = (const float*)d_in[6];
    const float* Wqa = (const float*)d_in[7];
    const float* Wqg = (const float*)d_in[8];
    const float* Wov = (const float*)d_in[9];
    const float* Wo  = (const float*)d_in[10];
    float* out = (float*)d_out;

    __nv_bfloat16 *hsh,*hsl,*woh,*wol,*ovh,*ovl,*och,*ocl,*gth,*gtl;
    SYMF(hsh,g_hs_h);  SYMF(hsl,g_hs_l);
    SYMF(woh,g_WoT_h); SYMF(wol,g_WoT_l);
    SYMF(ovh,g_WovT_h);SYMF(ovl,g_WovT_l);
    SYMF(och,g_oc_h);  SYMF(ocl,g_oc_l);
    SYMF(gth,g_gat_h); SYMF(gtl,g_gat_l);

    cudaFuncSetAttribute(prep_all, cudaFuncAttributeMaxDynamicSharedMemorySize, PREPW_SMEM);
    prep_all<<<17152, 256, PREPW_SMEM>>>(hs, pos, Wq, Wk, Wv, Wvc,
                                         Wqa, Wqg, Wkc, Wov, Wo);         // 1

    cudaFuncSetAttribute(gemm_one, cudaFuncAttributeMaxDynamicSharedMemorySize, GSMEM);
    cudaFuncSetAttribute(gemm_qkv, cudaFuncAttributeMaxDynamicSharedMemorySize, GSMEM);

    gemm_qkv<<<dim3(32,16,3), NTHR, GSMEM>>>(hsh, hsl);                   // 2

    knop<<<1, 32>>>();                                                    // 3 (spacer)

    cudaFuncSetAttribute(attn_mma, cudaFuncAttributeMaxDynamicSharedMemorySize, ATT_SMEM);
    attn_mma<<<dim3(S_/128, B_*NH), 256, ATT_SMEM>>>();                   // 4 (profiled)

    gemm_one<<<dim3(512,1), NTHR, GSMEM>>>(och, ocl, ovh, ovl, 64, 4, 128, 128,
                                           nullptr, gth, gtl);            // 5
    gemm_one<<<dim3(32,16), NTHR, GSMEM>>>(gth, gtl, woh, wol, HID, 0, HID, HID,
                                           out, nullptr, nullptr);        // 6
}